// round 12
// baseline (speedup 1.0000x reference)
#include <cuda_runtime.h>
#include <cuda_bf16.h>
#include <cuda_fp16.h>
#include <math.h>
#include <cstdint>

#define N_NODES 50000
#define N_EDGES 800000
#define NFEAT   512
#define NHID    256
#define NCLASS  128
#define N_UV    2048

// ---------------- scratch (device globals; no allocation allowed) ----------------
__device__ __nv_bfloat16 g_w1t_hi[NHID * NFEAT];
__device__ __nv_bfloat16 g_w1t_lo[NHID * NFEAT];
__device__ __half        g_s1h[N_NODES * NHID];     // support1 fp16
__device__ __half        g_w2t_hi[NCLASS * NHID];   // W2^T fp16 hi
__device__ __half        g_w2t_lo[NCLASS * NHID];   // W2^T fp16 lo
__device__ __half        g_s2h[N_NODES * NCLASS];   // support2 fp16
__device__ __nv_bfloat16 g_zuhi[N_UV * NCLASS];
__device__ __nv_bfloat16 g_zulo[N_UV * NCLASS];
__device__ __nv_bfloat16 g_zvhi[N_UV * NCLASS];
__device__ __nv_bfloat16 g_zvlo[N_UV * NCLASS];
__device__ int           g_rowptr[N_NODES + 1];

// ---------------- helpers ----------------
__device__ __forceinline__ uint32_t smem_to_u32(const void* p) {
    uint32_t a;
    asm("{ .reg .u64 t; cvta.to.shared.u64 t, %1; cvt.u32.u64 %0, t; }" : "=r"(a) : "l"(p));
    return a;
}

__device__ __forceinline__ void ldsm_x4(uint32_t* r, uint32_t addr) {
    asm volatile("ldmatrix.sync.aligned.m8n8.x4.shared.b16 {%0,%1,%2,%3}, [%4];"
                 : "=r"(r[0]), "=r"(r[1]), "=r"(r[2]), "=r"(r[3]) : "r"(addr));
}

__device__ __forceinline__ void mma_bf16(float* d, const uint32_t* a, const uint32_t* b) {
    asm volatile(
        "mma.sync.aligned.m16n8k16.row.col.f32.bf16.bf16.f32 "
        "{%0,%1,%2,%3}, {%4,%5,%6,%7}, {%8,%9}, {%0,%1,%2,%3};\n"
        : "+f"(d[0]), "+f"(d[1]), "+f"(d[2]), "+f"(d[3])
        : "r"(a[0]), "r"(a[1]), "r"(a[2]), "r"(a[3]), "r"(b[0]), "r"(b[1]));
}

__device__ __forceinline__ void mma_f16(float* d, const uint32_t* a, const uint32_t* b) {
    asm volatile(
        "mma.sync.aligned.m16n8k16.row.col.f32.f16.f16.f32 "
        "{%0,%1,%2,%3}, {%4,%5,%6,%7}, {%8,%9}, {%0,%1,%2,%3};\n"
        : "+f"(d[0]), "+f"(d[1]), "+f"(d[2]), "+f"(d[3])
        : "r"(a[0]), "r"(a[1]), "r"(a[2]), "r"(a[3]), "r"(b[0]), "r"(b[1]));
}

__device__ __forceinline__ void cp_async16(uint32_t dst, const void* src, int src_bytes) {
    asm volatile("cp.async.cg.shared.global [%0], [%1], 16, %2;"
                 :: "r"(dst), "l"(src), "r"(src_bytes) : "memory");
}
__device__ __forceinline__ void cp_commit() {
    asm volatile("cp.async.commit_group;" ::: "memory");
}
__device__ __forceinline__ void cp_wait1() {
    asm volatile("cp.async.wait_group 1;" ::: "memory");
}
__device__ __forceinline__ void cp_wait0() {
    asm volatile("cp.async.wait_group 0;" ::: "memory");
}

__device__ __forceinline__ void split_f32(float v, __nv_bfloat16& hi, __nv_bfloat16& lo) {
    hi = __float2bfloat16_rn(v);
    lo = __float2bfloat16_rn(v - __bfloat162float(hi));
}

__device__ __forceinline__ void split_f32h(float v, __half& hi, __half& lo) {
    hi = __float2half_rn(v);
    lo = __float2half_rn(v - __half2float(hi));
}

__device__ __forceinline__ void sts64(uint32_t addr, uint32_t a, uint32_t b) {
    asm volatile("st.shared.v2.b32 [%0], {%1, %2};" :: "r"(addr), "r"(a), "r"(b) : "memory");
}

__device__ __forceinline__ void sts128(uint32_t addr, uint4 v) {
    asm volatile("st.shared.v4.b32 [%0], {%1, %2, %3, %4};"
                 :: "r"(addr), "r"(v.x), "r"(v.y), "r"(v.z), "r"(v.w) : "memory");
}

// ---------------- prep: W1 bf16 split (transposed), W2 fp16 split (transposed), rowptr ----------------
#define NB_W     (((NFEAT * NHID + NHID * NCLASS) + 255) / 256)        // 640
#define NB_ROW   ((N_NODES + 1 + 255) / 256)                           // 196

__global__ __launch_bounds__(256) void prep_kernel(
    const float* __restrict__ W1, const float* __restrict__ W2,
    const int* __restrict__ adj_row)
{
    const int bid = blockIdx.x;
    if (bid < NB_W) {
        int i = bid * 256 + threadIdx.x;
        if (i < NFEAT * NHID) {
            int k = i / NHID, n = i % NHID;
            __nv_bfloat16 h, l;
            split_f32(W1[i], h, l);
            g_w1t_hi[(size_t)n * NFEAT + k] = h;
            g_w1t_lo[(size_t)n * NFEAT + k] = l;
        } else {
            int j = i - NFEAT * NHID;
            if (j < NHID * NCLASS) {
                int k = j / NCLASS, n = j % NCLASS;
                __half h, l;
                split_f32h(W2[j], h, l);
                g_w2t_hi[(size_t)n * NHID + k] = h;
                g_w2t_lo[(size_t)n * NHID + k] = l;
            }
        }
    } else {
        int i = (bid - NB_W) * 256 + threadIdx.x;
        if (i > N_NODES) return;
        int lo = 0, hi = N_EDGES;
        while (lo < hi) {
            int mid = (lo + hi) >> 1;
            if (adj_row[mid] < i) lo = mid + 1; else hi = mid;
        }
        g_rowptr[i] = lo;
    }
}

// ---------------- common tile constants ----------------
#define GSTRIDE 80                     // smem row stride in bytes (40 x 16-bit)
#define GTILE   (128 * GSTRIDE)        // 10240 bytes per operand tile
#define GBUF    (4 * GTILE)            // 4-tile buffer (bf16x3 kernels)

// fused kernel smem: A tile (128 x 256 fp16, stride 528B) + B double-buffer
#define ASTRIDE 528
#define A_BYTES (128 * ASTRIDE)        // 67584
#define BBUF2   (2 * GTILE)            // 20480 per stage
#define FUSED_SMEM (A_BYTES + 2 * BBUF2)   // 108544

// ---------------- GEMM1: C_fp16[M,N] = A_fp32 @ B^T, split A on the fly (bf16x3) ----------------
__global__ __launch_bounds__(256, 2) void mma_gemm_f32a_kernel(
    const float* __restrict__ A,
    const __nv_bfloat16* __restrict__ Bhi, const __nv_bfloat16* __restrict__ Blo,
    __half* __restrict__ C, int M, int N, int K)
{
    extern __shared__ char smem_raw[];
    const uint32_t sb = smem_to_u32(smem_raw);

    const int tid  = threadIdx.x;
    const int wid  = tid >> 5;
    const int lane = tid & 31;
    const int warp_m = wid & 3;
    const int warp_n = wid >> 2;
    const int bm = blockIdx.y * 128;
    const int bn = blockIdx.x * 128;

    float acc[2][8][4];
#pragma unroll
    for (int mt = 0; mt < 2; mt++)
#pragma unroll
        for (int nt = 0; nt < 8; nt++)
#pragma unroll
            for (int i = 0; i < 4; i++) acc[mt][nt][i] = 0.f;

    const int NC = K >> 5;

    float4 pa[4];
    auto ldgA = [&](int c) {
        const int k0 = c << 5;
#pragma unroll
        for (int i = 0; i < 4; i++) {
            const int s = tid + i * 256;
            const int row = s >> 3;
            const int seg = s & 7;
            const int ar = bm + row;
            if (ar < M)
                pa[i] = *reinterpret_cast<const float4*>(A + (size_t)ar * K + k0 + seg * 4);
            else
                pa[i] = make_float4(0.f, 0.f, 0.f, 0.f);
        }
    };
    auto stsA = [&](uint32_t bufbase) {
#pragma unroll
        for (int i = 0; i < 4; i++) {
            const int s = tid + i * 256;
            const int row = s >> 3;
            const int seg = s & 7;
            __nv_bfloat16 h0, h1, h2, h3, l0, l1, l2, l3;
            split_f32(pa[i].x, h0, l0); split_f32(pa[i].y, h1, l1);
            split_f32(pa[i].z, h2, l2); split_f32(pa[i].w, h3, l3);
            union { __nv_bfloat162 b2[2]; uint32_t u[2]; } H, L;
            H.b2[0] = __nv_bfloat162(h0, h1); H.b2[1] = __nv_bfloat162(h2, h3);
            L.b2[0] = __nv_bfloat162(l0, l1); L.b2[1] = __nv_bfloat162(l2, l3);
            const uint32_t off = row * GSTRIDE + seg * 8;
            sts64(bufbase + off, H.u[0], H.u[1]);
            sts64(bufbase + GTILE + off, L.u[0], L.u[1]);
        }
    };
    auto ldB = [&](int c, uint32_t bufbase) {
        const int k0 = c << 5;
#pragma unroll
        for (int i = 0; i < 2; i++) {
            const int s = tid + i * 256;
            const int row = s >> 2;
            const int seg = s & 3;
            const uint32_t soff = row * GSTRIDE + seg * 16;
            const size_t boff = (size_t)(bn + row) * K + k0 + seg * 8;
            cp_async16(bufbase + 2 * GTILE + soff, Bhi + boff, 16);
            cp_async16(bufbase + 3 * GTILE + soff, Blo + boff, 16);
        }
        cp_commit();
    };

    ldgA(0);
    ldB(0, sb);

    for (int c = 0; c < NC; c++) {
        const uint32_t bufbase = sb + (c & 1) * GBUF;
        stsA(bufbase);
        if (c + 1 < NC) {
            ldgA(c + 1);
            ldB(c + 1, sb + ((c + 1) & 1) * GBUF);
            cp_wait1();
        } else {
            cp_wait0();
        }
        __syncthreads();

        const uint32_t sA_hi = bufbase;
        const uint32_t sA_lo = bufbase + GTILE;
        const uint32_t sB_hi = bufbase + 2 * GTILE;
        const uint32_t sB_lo = bufbase + 3 * GTILE;

#pragma unroll
        for (int ks = 0; ks < 2; ks++) {
            const int kc = ks * 16;
            uint32_t ah[2][4], al[2][4];
#pragma unroll
            for (int mt = 0; mt < 2; mt++) {
                const int row = warp_m * 32 + mt * 16 + (lane & 15);
                const int col = kc + ((lane >> 4) << 3);
                const uint32_t off = row * GSTRIDE + col * 2;
                ldsm_x4(ah[mt], sA_hi + off);
                ldsm_x4(al[mt], sA_lo + off);
            }
#pragma unroll
            for (int half = 0; half < 2; half++) {
                uint32_t bh[4][2], bl[4][2];
#pragma unroll
                for (int bt = 0; bt < 2; bt++) {
                    const int nrow = warp_n * 64 + half * 32 + bt * 16
                                   + (lane & 7) + ((lane >> 4) & 1) * 8;
                    const int col  = kc + ((lane >> 3) & 1) * 8;
                    const uint32_t off = nrow * GSTRIDE + col * 2;
                    uint32_t t[4];
                    ldsm_x4(t, sB_hi + off);
                    bh[bt * 2][0] = t[0]; bh[bt * 2][1] = t[1];
                    bh[bt * 2 + 1][0] = t[2]; bh[bt * 2 + 1][1] = t[3];
                    ldsm_x4(t, sB_lo + off);
                    bl[bt * 2][0] = t[0]; bl[bt * 2][1] = t[1];
                    bl[bt * 2 + 1][0] = t[2]; bl[bt * 2 + 1][1] = t[3];
                }
#pragma unroll
                for (int mt = 0; mt < 2; mt++)
#pragma unroll
                    for (int j = 0; j < 4; j++) {
                        float* a = acc[mt][half * 4 + j];
                        mma_bf16(a, ah[mt], bh[j]);
                        mma_bf16(a, ah[mt], bl[j]);
                        mma_bf16(a, al[mt], bh[j]);
                    }
            }
        }
        __syncthreads();
    }

    const int cb = bn + warp_n * 64 + (lane & 3) * 2;
#pragma unroll
    for (int mt = 0; mt < 2; mt++) {
        const int row0 = bm + warp_m * 32 + mt * 16 + (lane >> 2);
#pragma unroll
        for (int h = 0; h < 2; h++) {
            const int row = row0 + h * 8;
            if (row >= M) continue;
            __half* dst = C + (size_t)row * N + cb;
#pragma unroll
            for (int nt = 0; nt < 8; nt++) {
                *reinterpret_cast<__half2*>(dst + nt * 8) =
                    __floats2half2_rn(acc[mt][nt][h * 2 + 0], acc[mt][nt][h * 2 + 1]);
            }
        }
    }
}

// ---------------- FUSED SpMM1 + GEMM2 ----------------
// Phase A: gather h tile (128 rows x K=256 fp16) = relu(A_adj @ s1 + b1) into smem.
// Phase B: s2[bm:bm+128, 0:128] = h_tile @ W2t^T (fp16 HMMA, hi+lo), fp16 out.
__global__ __launch_bounds__(256, 2) void spmm_gemm2_fused_kernel(
    const int* __restrict__ col, const float* __restrict__ val,
    const float* __restrict__ bias,
    const __half* __restrict__ Bhi, const __half* __restrict__ Blo,
    __half* __restrict__ C, int M)
{
    const int K = NHID;      // 256
    const int N = NCLASS;    // 128
    extern __shared__ char smem_raw[];
    const uint32_t sb  = smem_to_u32(smem_raw);
    const uint32_t sbA = sb;
    const uint32_t sbB = sb + A_BYTES;

    const int tid  = threadIdx.x;
    const int wid  = tid >> 5;
    const int lane = tid & 31;
    const int warp_m = wid & 3;
    const int warp_n = wid >> 2;
    const int bm = blockIdx.x * 128;

    auto ldB = [&](int c, uint32_t bufbase) {
        const int k0 = c << 5;
#pragma unroll
        for (int i = 0; i < 2; i++) {
            const int s = tid + i * 256;
            const int row = s >> 2;
            const int seg = s & 3;
            const uint32_t soff = row * GSTRIDE + seg * 16;
            const size_t boff = (size_t)row * K + k0 + seg * 8;
            cp_async16(bufbase + soff, Bhi + boff, 16);
            cp_async16(bufbase + GTILE + soff, Blo + boff, 16);
        }
        cp_commit();
    };

    // prefetch B chunk 0 — overlaps with the gather phase
    ldB(0, sbB);

    // ---- phase A: gather ----
    const uint4* __restrict__ X4 = reinterpret_cast<const uint4*>(g_s1h);
    for (int rr = 0; rr < 16; rr++) {
        const int rl = wid * 16 + rr;
        const int r = bm + rl;
        float acc[8];
#pragma unroll
        for (int i = 0; i < 8; i++) acc[i] = 0.f;
        if (r < M) {
            const int e0 = g_rowptr[r];
            const int e1 = g_rowptr[r + 1];
            int e = e0;
            for (; e + 2 <= e1; e += 2) {
                const int   c0 = __ldg(&col[e]);
                const int   c1 = __ldg(&col[e + 1]);
                const float w0 = __ldg(&val[e]);
                const float w1 = __ldg(&val[e + 1]);
                uint4 q0 = X4[(size_t)c0 * 32 + lane];
                uint4 q1 = X4[(size_t)c1 * 32 + lane];
                const __half2* h0 = reinterpret_cast<const __half2*>(&q0);
                const __half2* h1 = reinterpret_cast<const __half2*>(&q1);
#pragma unroll
                for (int j = 0; j < 4; j++) {
                    float2 f0 = __half22float2(h0[j]);
                    float2 f1 = __half22float2(h1[j]);
                    acc[j * 2 + 0] = fmaf(w0, f0.x, acc[j * 2 + 0]);
                    acc[j * 2 + 1] = fmaf(w0, f0.y, acc[j * 2 + 1]);
                    acc[j * 2 + 0] = fmaf(w1, f1.x, acc[j * 2 + 0]);
                    acc[j * 2 + 1] = fmaf(w1, f1.y, acc[j * 2 + 1]);
                }
            }
            if (e < e1) {
                const int   c0 = __ldg(&col[e]);
                const float w0 = __ldg(&val[e]);
                uint4 q0 = X4[(size_t)c0 * 32 + lane];
                const __half2* h0 = reinterpret_cast<const __half2*>(&q0);
#pragma unroll
                for (int j = 0; j < 4; j++) {
                    float2 f0 = __half22float2(h0[j]);
                    acc[j * 2 + 0] = fmaf(w0, f0.x, acc[j * 2 + 0]);
                    acc[j * 2 + 1] = fmaf(w0, f0.y, acc[j * 2 + 1]);
                }
            }
            const float4 b0 = reinterpret_cast<const float4*>(bias)[lane * 2 + 0];
            const float4 b1 = reinterpret_cast<const float4*>(bias)[lane * 2 + 1];
            acc[0] = fmaxf(acc[0] + b0.x, 0.f); acc[1] = fmaxf(acc[1] + b0.y, 0.f);
            acc[2] = fmaxf(acc[2] + b0.z, 0.f); acc[3] = fmaxf(acc[3] + b0.w, 0.f);
            acc[4] = fmaxf(acc[4] + b1.x, 0.f); acc[5] = fmaxf(acc[5] + b1.y, 0.f);
            acc[6] = fmaxf(acc[6] + b1.z, 0.f); acc[7] = fmaxf(acc[7] + b1.w, 0.f);
        }
        union { uint4 u; __half2 h[4]; } H;
#pragma unroll
        for (int j = 0; j < 4; j++)
            H.h[j] = __floats2half2_rn(acc[j * 2 + 0], acc[j * 2 + 1]);
        sts128(sbA + rl * ASTRIDE + lane * 16, H.u);
    }
    __syncthreads();

    // ---- phase B: GEMM ----
    float acc[2][8][4];
#pragma unroll
    for (int mt = 0; mt < 2; mt++)
#pragma unroll
        for (int nt = 0; nt < 8; nt++)
#pragma unroll
            for (int i = 0; i < 4; i++) acc[mt][nt][i] = 0.f;

    const int NC = K >> 5;   // 8
    for (int c = 0; c < NC; c++) {
        const uint32_t bufbase = sbB + (c & 1) * BBUF2;
        if (c + 1 < NC) {
            ldB(c + 1, sbB + ((c + 1) & 1) * BBUF2);
            cp_wait1();
        } else {
            cp_wait0();
        }
        __syncthreads();

        const uint32_t sB_hi = bufbase;
        const uint32_t sB_lo = bufbase + GTILE;

#pragma unroll
        for (int ks = 0; ks < 2; ks++) {
            const int kc = ks * 16;
            uint32_t ah[2][4];
#pragma unroll
            for (int mt = 0; mt < 2; mt++) {
                const int row = warp_m * 32 + mt * 16 + (lane & 15);
                const int colk = (c << 5) + kc + ((lane >> 4) << 3);
                ldsm_x4(ah[mt], sbA + row * ASTRIDE + colk * 2);
            }
#pragma unroll
            for (int half = 0; half < 2; half++) {
                uint32_t bh[4][2], bl[4][2];
#pragma unroll
                for (int bt = 0; bt < 2; bt++) {
                    const int nrow = warp_n * 64 + half * 32 + bt * 16
                                   + (lane & 7) + ((lane >> 4) & 1) * 8;
                    const int colb = kc + ((lane >> 3) & 1) * 8;
                    const uint32_t off = nrow * GSTRIDE + colb * 2;
                    uint32_t t[4];
                    ldsm_x4(t, sB_hi + off);
                    bh[bt * 2][0] = t[0]; bh[bt * 2][1] = t[1];
                    bh[bt * 2 + 1][0] = t[2]; bh[bt * 2 + 1][1] = t[3];
                    ldsm_x4(t, sB_lo + off);
                    bl[bt * 2][0] = t[0]; bl[bt * 2][1] = t[1];
                    bl[bt * 2 + 1][0] = t[2]; bl[bt * 2 + 1][1] = t[3];
                }
#pragma unroll
                for (int mt = 0; mt < 2; mt++)
#pragma unroll
                    for (int j = 0; j < 4; j++) {
                        float* a = acc[mt][half * 4 + j];
                        mma_f16(a, ah[mt], bh[j]);
                        mma_f16(a, ah[mt], bl[j]);
                    }
            }
        }
        __syncthreads();
    }

    const int cb = warp_n * 64 + (lane & 3) * 2;
#pragma unroll
    for (int mt = 0; mt < 2; mt++) {
        const int row0 = bm + warp_m * 32 + mt * 16 + (lane >> 2);
#pragma unroll
        for (int h = 0; h < 2; h++) {
            const int row = row0 + h * 8;
            if (row >= M) continue;
            __half* dst = C + (size_t)row * N + cb;
#pragma unroll
            for (int nt = 0; nt < 8; nt++) {
                *reinterpret_cast<__half2*>(dst + nt * 8) =
                    __floats2half2_rn(acc[mt][nt][h * 2 + 0], acc[mt][nt][h * 2 + 1]);
            }
        }
    }
}

// ---------------- GEMM3: sigmoid(A @ B^T), bf16x3, fp32 out ----------------
__global__ __launch_bounds__(256, 2) void mma_gemm_kernel(
    const __nv_bfloat16* __restrict__ Ahi, const __nv_bfloat16* __restrict__ Alo,
    const __nv_bfloat16* __restrict__ Bhi, const __nv_bfloat16* __restrict__ Blo,
    float* __restrict__ C, int M, int N, int K)
{
    extern __shared__ char smem_raw[];
    const uint32_t sb = smem_to_u32(smem_raw);

    const int tid  = threadIdx.x;
    const int wid  = tid >> 5;
    const int lane = tid & 31;
    const int warp_m = wid & 3;
    const int warp_n = wid >> 2;
    const int bm = blockIdx.y * 128;
    const int bn = blockIdx.x * 128;

    float acc[2][8][4];
#pragma unroll
    for (int mt = 0; mt < 2; mt++)
#pragma unroll
        for (int nt = 0; nt < 8; nt++)
#pragma unroll
            for (int i = 0; i < 4; i++) acc[mt][nt][i] = 0.f;

    const int NC = K >> 5;

    auto load_chunk = [&](int c, uint32_t bufbase) {
        const int k0 = c << 5;
#pragma unroll
        for (int i = 0; i < 2; i++) {
            const int s = tid + i * 256;
            const int row = s >> 2;
            const int seg = s & 3;
            const uint32_t soff = row * GSTRIDE + seg * 16;
            const size_t aoff = (size_t)(bm + row) * K + k0 + seg * 8;
            cp_async16(bufbase + 0 * GTILE + soff, Ahi + aoff, 16);
            cp_async16(bufbase + 1 * GTILE + soff, Alo + aoff, 16);
            const size_t boff = (size_t)(bn + row) * K + k0 + seg * 8;
            cp_async16(bufbase + 2 * GTILE + soff, Bhi + boff, 16);
            cp_async16(bufbase + 3 * GTILE + soff, Blo + boff, 16);
        }
        cp_commit();
    };

    load_chunk(0, sb);

    for (int c = 0; c < NC; c++) {
        const uint32_t bufbase = sb + (c & 1) * GBUF;
        if (c + 1 < NC) {
            load_chunk(c + 1, sb + ((c + 1) & 1) * GBUF);
            cp_wait1();
        } else {
            cp_wait0();
        }
        __syncthreads();

        const uint32_t sA_hi = bufbase + 0 * GTILE;
        const uint32_t sA_lo = bufbase + 1 * GTILE;
        const uint32_t sB_hi = bufbase + 2 * GTILE;
        const uint32_t sB_lo = bufbase + 3 * GTILE;

#pragma unroll
        for (int ks = 0; ks < 2; ks++) {
            const int kc = ks * 16;
            uint32_t ah[2][4], al[2][4];
#pragma unroll
            for (int mt = 0; mt < 2; mt++) {
                const int row = warp_m * 32 + mt * 16 + (lane & 15);
                const int col = kc + ((lane >> 4) << 3);
                const uint32_t off = row * GSTRIDE + col * 2;
                ldsm_x4(ah[mt], sA_hi + off);
                ldsm_x4(al[mt], sA_lo + off);
            }
#pragma unroll
            for (int half = 0; half < 2; half++) {
                uint32_t bh[4][2], bl[4][2];
#pragma unroll
                for (int bt = 0; bt < 2; bt++) {
                    const int nrow = warp_n * 64 + half * 32 + bt * 16
                                   + (lane & 7) + ((lane >> 4) & 1) * 8;
                    const int col  = kc + ((lane >> 3) & 1) * 8;
                    const uint32_t off = nrow * GSTRIDE + col * 2;
                    uint32_t t[4];
                    ldsm_x4(t, sB_hi + off);
                    bh[bt * 2][0] = t[0]; bh[bt * 2][1] = t[1];
                    bh[bt * 2 + 1][0] = t[2]; bh[bt * 2 + 1][1] = t[3];
                    ldsm_x4(t, sB_lo + off);
                    bl[bt * 2][0] = t[0]; bl[bt * 2][1] = t[1];
                    bl[bt * 2 + 1][0] = t[2]; bl[bt * 2 + 1][1] = t[3];
                }
#pragma unroll
                for (int mt = 0; mt < 2; mt++)
#pragma unroll
                    for (int j = 0; j < 4; j++) {
                        float* a = acc[mt][half * 4 + j];
                        mma_bf16(a, ah[mt], bh[j]);
                        mma_bf16(a, ah[mt], bl[j]);
                        mma_bf16(a, al[mt], bh[j]);
                    }
            }
        }
        __syncthreads();
    }

    const int cb = bn + warp_n * 64 + (lane & 3) * 2;
#pragma unroll
    for (int mt = 0; mt < 2; mt++) {
        const int row0 = bm + warp_m * 32 + mt * 16 + (lane >> 2);
#pragma unroll
        for (int h = 0; h < 2; h++) {
            const int row = row0 + h * 8;
            float* dst = C + (size_t)row * N + cb;
#pragma unroll
            for (int nt = 0; nt < 8; nt++) {
                float v0 = acc[mt][nt][h * 2 + 0];
                float v1 = acc[mt][nt][h * 2 + 1];
                v0 = 1.f / (1.f + expf(-v0));
                v1 = 1.f / (1.f + expf(-v1));
                *reinterpret_cast<float2*>(dst + nt * 8) = make_float2(v0, v1);
            }
        }
    }
}

// ---------------- fused z-row + edge embedding for u/v only (fp16 gather) ----------------
__global__ __launch_bounds__(NCLASS) void zuv_kernel(
    const int* __restrict__ u, const int* __restrict__ v,
    const int* __restrict__ col, const float* __restrict__ val,
    const float* __restrict__ b2, const float* __restrict__ We)
{
    const bool is_u = blockIdx.x < N_UV;
    const int b = is_u ? blockIdx.x : blockIdx.x - N_UV;
    const int r = is_u ? __ldg(&u[b]) : __ldg(&v[b]);
    const int t = threadIdx.x;            // 0..127

    const int e0 = g_rowptr[r];
    const int e1 = g_rowptr[r + 1];
    float acc[4];
#pragma unroll
    for (int i = 0; i < 4; i++) acc[i] = 0.f;
    int e = e0;
    for (; e + 4 <= e1; e += 4) {
#pragma unroll
        for (int i = 0; i < 4; i++) {
            const int   c0 = __ldg(&col[e + i]);
            const float w0 = __ldg(&val[e + i]);
            acc[i] = fmaf(w0, __half2float(g_s2h[(size_t)c0 * NCLASS + t]), acc[i]);
        }
    }
    for (; e < e1; e++) {
        acc[0] = fmaf(__ldg(&val[e]),
                      __half2float(g_s2h[(size_t)__ldg(&col[e]) * NCLASS + t]), acc[0]);
    }
    const float zt = acc[0] + acc[1] + acc[2] + acc[3] + __ldg(&b2[t]);

    __nv_bfloat16 h, l;
    if (is_u) {
        __shared__ float zrow[NCLASS];
        zrow[t] = zt;
        __syncthreads();
        float s = 0.f;
#pragma unroll 8
        for (int k = 0; k < NCLASS; k++)
            s = fmaf(zrow[k], __ldg(&We[(size_t)t * NCLASS + k]), s);
        split_f32(s, h, l);
        g_zuhi[(size_t)b * NCLASS + t] = h;
        g_zulo[(size_t)b * NCLASS + t] = l;
    } else {
        split_f32(zt, h, l);
        g_zvhi[(size_t)b * NCLASS + t] = h;
        g_zvlo[(size_t)b * NCLASS + t] = l;
    }
}

// ---------------- launch ----------------
extern "C" void kernel_launch(void* const* d_in, const int* in_sizes, int n_in,
                              void* d_out, int out_size)
{
    const int*   u       = (const int*)d_in[0];
    const int*   v       = (const int*)d_in[1];
    const float* x       = (const float*)d_in[2];
    const int*   adj_row = (const int*)d_in[3];
    const int*   adj_col = (const int*)d_in[4];
    const float* adj_val = (const float*)d_in[5];
    const float* W1      = (const float*)d_in[6];
    const float* b1      = (const float*)d_in[7];
    const float* W2      = (const float*)d_in[8];
    const float* b2      = (const float*)d_in[9];
    const float* We      = (const float*)d_in[10];
    float* out = (float*)d_out;

    __nv_bfloat16 *w1th, *w1tl, *zuh, *zul, *zvh, *zvl;
    __half *s1h, *w2th, *w2tl, *s2h;
    cudaGetSymbolAddress((void**)&w1th, g_w1t_hi);
    cudaGetSymbolAddress((void**)&w1tl, g_w1t_lo);
    cudaGetSymbolAddress((void**)&s1h, g_s1h);
    cudaGetSymbolAddress((void**)&w2th, g_w2t_hi);
    cudaGetSymbolAddress((void**)&w2tl, g_w2t_lo);
    cudaGetSymbolAddress((void**)&s2h, g_s2h);
    cudaGetSymbolAddress((void**)&zuh, g_zuhi);
    cudaGetSymbolAddress((void**)&zul, g_zulo);
    cudaGetSymbolAddress((void**)&zvh, g_zvhi);
    cudaGetSymbolAddress((void**)&zvl, g_zvlo);

    const int SMEM4 = 2 * GBUF;    // 81920
    cudaFuncSetAttribute(mma_gemm_kernel, cudaFuncAttributeMaxDynamicSharedMemorySize, SMEM4);
    cudaFuncSetAttribute(mma_gemm_f32a_kernel, cudaFuncAttributeMaxDynamicSharedMemorySize, SMEM4);
    cudaFuncSetAttribute(spmm_gemm2_fused_kernel, cudaFuncAttributeMaxDynamicSharedMemorySize, FUSED_SMEM);

    // 1. prep: weight transpose/split + rowptr
    prep_kernel<<<NB_W + NB_ROW, 256>>>(W1, W2, adj_row);

    // 2. support1 = x @ W1  (fp32 A on-the-fly bf16x3, fp16 output)
    {
        dim3 grid(NHID / 128, (N_NODES + 127) / 128);
        mma_gemm_f32a_kernel<<<grid, 256, SMEM4>>>(x, w1th, w1tl, s1h,
                                                   N_NODES, NHID, NFEAT);
    }

    // 3+4. fused: h = relu(A @ s1 + b1) gathered in smem, then s2 = h @ W2 (fp16 HMMA)
    {
        dim3 grid((N_NODES + 127) / 128);
        spmm_gemm2_fused_kernel<<<grid, 256, FUSED_SMEM>>>(adj_col, adj_val, b1,
                                                           w2th, w2tl, s2h, N_NODES);
    }

    // 5. fused: z-rows for u/v only, + We rotation + bf16 split
    zuv_kernel<<<2 * N_UV, NCLASS>>>(u, v, adj_col, adj_val, b2, We);

    // 6. out = sigmoid(zu @ zv^T)  (bf16x3, fused sigmoid)
    {
        dim3 grid(N_UV / 128, N_UV / 128);
        mma_gemm_kernel<<<grid, 256, SMEM4>>>(zuh, zul, zvh, zvl, out,
                                              N_UV, N_UV, NCLASS);
    }
}

// round 13
// speedup vs baseline: 1.8406x; 1.8406x over previous
#include <cuda_runtime.h>
#include <cuda_bf16.h>
#include <cuda_fp16.h>
#include <math.h>
#include <cstdint>

#define N_NODES 50000
#define N_EDGES 800000
#define NFEAT   512
#define NHID    256
#define NCLASS  128
#define N_UV    2048

// ---------------- scratch (device globals; no allocation allowed) ----------------
__device__ __nv_bfloat16 g_w1t_hi[NHID * NFEAT];
__device__ __nv_bfloat16 g_w1t_lo[NHID * NFEAT];
__device__ __half        g_s1h[N_NODES * NHID];     // support1 fp16
__device__ __half        g_hf[N_NODES * NHID];      // h fp16
__device__ __half        g_w2t_hi[NCLASS * NHID];   // W2^T fp16 hi
__device__ __half        g_w2t_lo[NCLASS * NHID];   // W2^T fp16 lo
__device__ __half        g_s2h[N_NODES * NCLASS];   // support2 fp16
__device__ float         g_weT[NCLASS * NCLASS];    // We^T (coalesced access in zuv)
__device__ __nv_bfloat16 g_zuhi[N_UV * NCLASS];
__device__ __nv_bfloat16 g_zulo[N_UV * NCLASS];
__device__ __nv_bfloat16 g_zvhi[N_UV * NCLASS];
__device__ __nv_bfloat16 g_zvlo[N_UV * NCLASS];
__device__ int           g_rowptr[N_NODES + 1];

// ---------------- helpers ----------------
__device__ __forceinline__ uint32_t smem_to_u32(const void* p) {
    uint32_t a;
    asm("{ .reg .u64 t; cvta.to.shared.u64 t, %1; cvt.u32.u64 %0, t; }" : "=r"(a) : "l"(p));
    return a;
}

__device__ __forceinline__ void ldsm_x4(uint32_t* r, uint32_t addr) {
    asm volatile("ldmatrix.sync.aligned.m8n8.x4.shared.b16 {%0,%1,%2,%3}, [%4];"
                 : "=r"(r[0]), "=r"(r[1]), "=r"(r[2]), "=r"(r[3]) : "r"(addr));
}

__device__ __forceinline__ void mma_bf16(float* d, const uint32_t* a, const uint32_t* b) {
    asm volatile(
        "mma.sync.aligned.m16n8k16.row.col.f32.bf16.bf16.f32 "
        "{%0,%1,%2,%3}, {%4,%5,%6,%7}, {%8,%9}, {%0,%1,%2,%3};\n"
        : "+f"(d[0]), "+f"(d[1]), "+f"(d[2]), "+f"(d[3])
        : "r"(a[0]), "r"(a[1]), "r"(a[2]), "r"(a[3]), "r"(b[0]), "r"(b[1]));
}

__device__ __forceinline__ void mma_f16(float* d, const uint32_t* a, const uint32_t* b) {
    asm volatile(
        "mma.sync.aligned.m16n8k16.row.col.f32.f16.f16.f32 "
        "{%0,%1,%2,%3}, {%4,%5,%6,%7}, {%8,%9}, {%0,%1,%2,%3};\n"
        : "+f"(d[0]), "+f"(d[1]), "+f"(d[2]), "+f"(d[3])
        : "r"(a[0]), "r"(a[1]), "r"(a[2]), "r"(a[3]), "r"(b[0]), "r"(b[1]));
}

__device__ __forceinline__ void cp_async16(uint32_t dst, const void* src, int src_bytes) {
    asm volatile("cp.async.cg.shared.global [%0], [%1], 16, %2;"
                 :: "r"(dst), "l"(src), "r"(src_bytes) : "memory");
}
__device__ __forceinline__ void cp_commit() {
    asm volatile("cp.async.commit_group;" ::: "memory");
}
__device__ __forceinline__ void cp_wait1() {
    asm volatile("cp.async.wait_group 1;" ::: "memory");
}
__device__ __forceinline__ void cp_wait0() {
    asm volatile("cp.async.wait_group 0;" ::: "memory");
}

__device__ __forceinline__ void split_f32(float v, __nv_bfloat16& hi, __nv_bfloat16& lo) {
    hi = __float2bfloat16_rn(v);
    lo = __float2bfloat16_rn(v - __bfloat162float(hi));
}

__device__ __forceinline__ void split_f32h(float v, __half& hi, __half& lo) {
    hi = __float2half_rn(v);
    lo = __float2half_rn(v - __half2float(hi));
}

__device__ __forceinline__ void sts64(uint32_t addr, uint32_t a, uint32_t b) {
    asm volatile("st.shared.v2.b32 [%0], {%1, %2};" :: "r"(addr), "r"(a), "r"(b) : "memory");
}

// ---------------- prep: W1 bf16 split (T), W2 fp16 split (T), We^T, rowptr ----------------
#define NB_W     (((NFEAT * NHID + NHID * NCLASS) + 255) / 256)        // 640
#define NB_WE    ((NCLASS * NCLASS) / 256)                             // 64
#define NB_ROW   ((N_NODES + 1 + 255) / 256)                           // 196

__global__ __launch_bounds__(256) void prep_kernel(
    const float* __restrict__ W1, const float* __restrict__ W2,
    const float* __restrict__ We, const int* __restrict__ adj_row)
{
    const int bid = blockIdx.x;
    if (bid < NB_W) {
        int i = bid * 256 + threadIdx.x;
        if (i < NFEAT * NHID) {
            int k = i / NHID, n = i % NHID;
            __nv_bfloat16 h, l;
            split_f32(W1[i], h, l);
            g_w1t_hi[(size_t)n * NFEAT + k] = h;
            g_w1t_lo[(size_t)n * NFEAT + k] = l;
        } else {
            int j = i - NFEAT * NHID;
            if (j < NHID * NCLASS) {
                int k = j / NCLASS, n = j % NCLASS;
                __half h, l;
                split_f32h(W2[j], h, l);
                g_w2t_hi[(size_t)n * NHID + k] = h;
                g_w2t_lo[(size_t)n * NHID + k] = l;
            }
        }
    } else if (bid < NB_W + NB_WE) {
        int i = (bid - NB_W) * 256 + threadIdx.x;    // i = t*NCLASS + k
        int t = i / NCLASS, k = i % NCLASS;
        g_weT[(size_t)k * NCLASS + t] = We[i];
    } else {
        int i = (bid - NB_W - NB_WE) * 256 + threadIdx.x;
        if (i > N_NODES) return;
        int lo = 0, hi = N_EDGES;
        while (lo < hi) {
            int mid = (lo + hi) >> 1;
            if (adj_row[mid] < i) lo = mid + 1; else hi = mid;
        }
        g_rowptr[i] = lo;
    }
}

// ---------------- common tile constants ----------------
#define GSTRIDE 80                     // smem row stride in bytes (40 x 16-bit)
#define GTILE   (128 * GSTRIDE)        // 10240 bytes per operand tile
#define GBUF    (4 * GTILE)            // 4-tile buffer (bf16x3 kernels)
#define GBUF3   (3 * GTILE)            // 3-tile buffer (f16 A-single kernel)

// ---------------- GEMM1: C_fp16[M,N] = A_fp32 @ B^T, split A on the fly (bf16x3) ----------------
__global__ __launch_bounds__(256, 2) void mma_gemm_f32a_kernel(
    const float* __restrict__ A,
    const __nv_bfloat16* __restrict__ Bhi, const __nv_bfloat16* __restrict__ Blo,
    __half* __restrict__ C, int M, int N, int K)
{
    extern __shared__ char smem_raw[];
    const uint32_t sb = smem_to_u32(smem_raw);

    const int tid  = threadIdx.x;
    const int wid  = tid >> 5;
    const int lane = tid & 31;
    const int warp_m = wid & 3;
    const int warp_n = wid >> 2;
    const int bm = blockIdx.y * 128;
    const int bn = blockIdx.x * 128;

    float acc[2][8][4];
#pragma unroll
    for (int mt = 0; mt < 2; mt++)
#pragma unroll
        for (int nt = 0; nt < 8; nt++)
#pragma unroll
            for (int i = 0; i < 4; i++) acc[mt][nt][i] = 0.f;

    const int NC = K >> 5;

    float4 pa[4];
    auto ldgA = [&](int c) {
        const int k0 = c << 5;
#pragma unroll
        for (int i = 0; i < 4; i++) {
            const int s = tid + i * 256;
            const int row = s >> 3;
            const int seg = s & 7;
            const int ar = bm + row;
            if (ar < M)
                pa[i] = *reinterpret_cast<const float4*>(A + (size_t)ar * K + k0 + seg * 4);
            else
                pa[i] = make_float4(0.f, 0.f, 0.f, 0.f);
        }
    };
    auto stsA = [&](uint32_t bufbase) {
#pragma unroll
        for (int i = 0; i < 4; i++) {
            const int s = tid + i * 256;
            const int row = s >> 3;
            const int seg = s & 7;
            __nv_bfloat16 h0, h1, h2, h3, l0, l1, l2, l3;
            split_f32(pa[i].x, h0, l0); split_f32(pa[i].y, h1, l1);
            split_f32(pa[i].z, h2, l2); split_f32(pa[i].w, h3, l3);
            union { __nv_bfloat162 b2[2]; uint32_t u[2]; } H, L;
            H.b2[0] = __nv_bfloat162(h0, h1); H.b2[1] = __nv_bfloat162(h2, h3);
            L.b2[0] = __nv_bfloat162(l0, l1); L.b2[1] = __nv_bfloat162(l2, l3);
            const uint32_t off = row * GSTRIDE + seg * 8;
            sts64(bufbase + off, H.u[0], H.u[1]);
            sts64(bufbase + GTILE + off, L.u[0], L.u[1]);
        }
    };
    auto ldB = [&](int c, uint32_t bufbase) {
        const int k0 = c << 5;
#pragma unroll
        for (int i = 0; i < 2; i++) {
            const int s = tid + i * 256;
            const int row = s >> 2;
            const int seg = s & 3;
            const uint32_t soff = row * GSTRIDE + seg * 16;
            const size_t boff = (size_t)(bn + row) * K + k0 + seg * 8;
            cp_async16(bufbase + 2 * GTILE + soff, Bhi + boff, 16);
            cp_async16(bufbase + 3 * GTILE + soff, Blo + boff, 16);
        }
        cp_commit();
    };

    ldgA(0);
    ldB(0, sb);

    for (int c = 0; c < NC; c++) {
        const uint32_t bufbase = sb + (c & 1) * GBUF;
        stsA(bufbase);
        if (c + 1 < NC) {
            ldgA(c + 1);
            ldB(c + 1, sb + ((c + 1) & 1) * GBUF);
            cp_wait1();
        } else {
            cp_wait0();
        }
        __syncthreads();

        const uint32_t sA_hi = bufbase;
        const uint32_t sA_lo = bufbase + GTILE;
        const uint32_t sB_hi = bufbase + 2 * GTILE;
        const uint32_t sB_lo = bufbase + 3 * GTILE;

#pragma unroll
        for (int ks = 0; ks < 2; ks++) {
            const int kc = ks * 16;
            uint32_t ah[2][4], al[2][4];
#pragma unroll
            for (int mt = 0; mt < 2; mt++) {
                const int row = warp_m * 32 + mt * 16 + (lane & 15);
                const int col = kc + ((lane >> 4) << 3);
                const uint32_t off = row * GSTRIDE + col * 2;
                ldsm_x4(ah[mt], sA_hi + off);
                ldsm_x4(al[mt], sA_lo + off);
            }
#pragma unroll
            for (int half = 0; half < 2; half++) {
                uint32_t bh[4][2], bl[4][2];
#pragma unroll
                for (int bt = 0; bt < 2; bt++) {
                    const int nrow = warp_n * 64 + half * 32 + bt * 16
                                   + (lane & 7) + ((lane >> 4) & 1) * 8;
                    const int col  = kc + ((lane >> 3) & 1) * 8;
                    const uint32_t off = nrow * GSTRIDE + col * 2;
                    uint32_t t[4];
                    ldsm_x4(t, sB_hi + off);
                    bh[bt * 2][0] = t[0]; bh[bt * 2][1] = t[1];
                    bh[bt * 2 + 1][0] = t[2]; bh[bt * 2 + 1][1] = t[3];
                    ldsm_x4(t, sB_lo + off);
                    bl[bt * 2][0] = t[0]; bl[bt * 2][1] = t[1];
                    bl[bt * 2 + 1][0] = t[2]; bl[bt * 2 + 1][1] = t[3];
                }
#pragma unroll
                for (int mt = 0; mt < 2; mt++)
#pragma unroll
                    for (int j = 0; j < 4; j++) {
                        float* a = acc[mt][half * 4 + j];
                        mma_bf16(a, ah[mt], bh[j]);
                        mma_bf16(a, ah[mt], bl[j]);
                        mma_bf16(a, al[mt], bh[j]);
                    }
            }
        }
        __syncthreads();
    }

    const int cb = bn + warp_n * 64 + (lane & 3) * 2;
#pragma unroll
    for (int mt = 0; mt < 2; mt++) {
        const int row0 = bm + warp_m * 32 + mt * 16 + (lane >> 2);
#pragma unroll
        for (int h = 0; h < 2; h++) {
            const int row = row0 + h * 8;
            if (row >= M) continue;
            __half* dst = C + (size_t)row * N + cb;
#pragma unroll
            for (int nt = 0; nt < 8; nt++) {
                *reinterpret_cast<__half2*>(dst + nt * 8) =
                    __floats2half2_rn(acc[mt][nt][h * 2 + 0], acc[mt][nt][h * 2 + 1]);
            }
        }
    }
}

// ---------------- GEMM2: C_fp16[M,N] = A_fp16 @ (Bhi+Blo)^T, fp16 HMMA (2 MMAs) ----------------
__global__ __launch_bounds__(256, 2) void mma_gemm_f16a_kernel(
    const __half* __restrict__ A,
    const __half* __restrict__ Bhi, const __half* __restrict__ Blo,
    __half* __restrict__ C, int M, int N, int K)
{
    extern __shared__ char smem_raw[];
    const uint32_t sb = smem_to_u32(smem_raw);

    const int tid  = threadIdx.x;
    const int wid  = tid >> 5;
    const int lane = tid & 31;
    const int warp_m = wid & 3;
    const int warp_n = wid >> 2;
    const int bm = blockIdx.y * 128;
    const int bn = blockIdx.x * 128;

    float acc[2][8][4];
#pragma unroll
    for (int mt = 0; mt < 2; mt++)
#pragma unroll
        for (int nt = 0; nt < 8; nt++)
#pragma unroll
            for (int i = 0; i < 4; i++) acc[mt][nt][i] = 0.f;

    const int NC = K >> 5;

    auto load_chunk = [&](int c, uint32_t bufbase) {
        const int k0 = c << 5;
#pragma unroll
        for (int i = 0; i < 2; i++) {
            const int s = tid + i * 256;
            const int row = s >> 2;
            const int seg = s & 3;
            const uint32_t soff = row * GSTRIDE + seg * 16;
            const int ar = bm + row;
            const int okA = (ar < M) ? 16 : 0;
            const int arc = okA ? ar : 0;
            cp_async16(bufbase + soff, A + (size_t)arc * K + k0 + seg * 8, okA);
            const size_t boff = (size_t)(bn + row) * K + k0 + seg * 8;
            cp_async16(bufbase + 1 * GTILE + soff, Bhi + boff, 16);
            cp_async16(bufbase + 2 * GTILE + soff, Blo + boff, 16);
        }
        cp_commit();
    };

    load_chunk(0, sb);

    for (int c = 0; c < NC; c++) {
        const uint32_t bufbase = sb + (c & 1) * GBUF3;
        if (c + 1 < NC) {
            load_chunk(c + 1, sb + ((c + 1) & 1) * GBUF3);
            cp_wait1();
        } else {
            cp_wait0();
        }
        __syncthreads();

        const uint32_t sA   = bufbase;
        const uint32_t sB_hi = bufbase + 1 * GTILE;
        const uint32_t sB_lo = bufbase + 2 * GTILE;

#pragma unroll
        for (int ks = 0; ks < 2; ks++) {
            const int kc = ks * 16;
            uint32_t ah[2][4];
#pragma unroll
            for (int mt = 0; mt < 2; mt++) {
                const int row = warp_m * 32 + mt * 16 + (lane & 15);
                const int col = kc + ((lane >> 4) << 3);
                ldsm_x4(ah[mt], sA + row * GSTRIDE + col * 2);
            }
#pragma unroll
            for (int half = 0; half < 2; half++) {
                uint32_t bh[4][2], bl[4][2];
#pragma unroll
                for (int bt = 0; bt < 2; bt++) {
                    const int nrow = warp_n * 64 + half * 32 + bt * 16
                                   + (lane & 7) + ((lane >> 4) & 1) * 8;
                    const int col  = kc + ((lane >> 3) & 1) * 8;
                    const uint32_t off = nrow * GSTRIDE + col * 2;
                    uint32_t t[4];
                    ldsm_x4(t, sB_hi + off);
                    bh[bt * 2][0] = t[0]; bh[bt * 2][1] = t[1];
                    bh[bt * 2 + 1][0] = t[2]; bh[bt * 2 + 1][1] = t[3];
                    ldsm_x4(t, sB_lo + off);
                    bl[bt * 2][0] = t[0]; bl[bt * 2][1] = t[1];
                    bl[bt * 2 + 1][0] = t[2]; bl[bt * 2 + 1][1] = t[3];
                }
#pragma unroll
                for (int mt = 0; mt < 2; mt++)
#pragma unroll
                    for (int j = 0; j < 4; j++) {
                        float* a = acc[mt][half * 4 + j];
                        mma_f16(a, ah[mt], bh[j]);
                        mma_f16(a, ah[mt], bl[j]);
                    }
            }
        }
        __syncthreads();
    }

    const int cb = bn + warp_n * 64 + (lane & 3) * 2;
#pragma unroll
    for (int mt = 0; mt < 2; mt++) {
        const int row0 = bm + warp_m * 32 + mt * 16 + (lane >> 2);
#pragma unroll
        for (int h = 0; h < 2; h++) {
            const int row = row0 + h * 8;
            if (row >= M) continue;
            __half* dst = C + (size_t)row * N + cb;
#pragma unroll
            for (int nt = 0; nt < 8; nt++) {
                *reinterpret_cast<__half2*>(dst + nt * 8) =
                    __floats2half2_rn(acc[mt][nt][h * 2 + 0], acc[mt][nt][h * 2 + 1]);
            }
        }
    }
}

// ---------------- GEMM3: sigmoid(A @ B^T), bf16x3, fp32 out ----------------
__global__ __launch_bounds__(256, 2) void mma_gemm_kernel(
    const __nv_bfloat16* __restrict__ Ahi, const __nv_bfloat16* __restrict__ Alo,
    const __nv_bfloat16* __restrict__ Bhi, const __nv_bfloat16* __restrict__ Blo,
    float* __restrict__ C, int M, int N, int K)
{
    extern __shared__ char smem_raw[];
    const uint32_t sb = smem_to_u32(smem_raw);

    const int tid  = threadIdx.x;
    const int wid  = tid >> 5;
    const int lane = tid & 31;
    const int warp_m = wid & 3;
    const int warp_n = wid >> 2;
    const int bm = blockIdx.y * 128;
    const int bn = blockIdx.x * 128;

    float acc[2][8][4];
#pragma unroll
    for (int mt = 0; mt < 2; mt++)
#pragma unroll
        for (int nt = 0; nt < 8; nt++)
#pragma unroll
            for (int i = 0; i < 4; i++) acc[mt][nt][i] = 0.f;

    const int NC = K >> 5;

    auto load_chunk = [&](int c, uint32_t bufbase) {
        const int k0 = c << 5;
#pragma unroll
        for (int i = 0; i < 2; i++) {
            const int s = tid + i * 256;
            const int row = s >> 2;
            const int seg = s & 3;
            const uint32_t soff = row * GSTRIDE + seg * 16;
            const size_t aoff = (size_t)(bm + row) * K + k0 + seg * 8;
            cp_async16(bufbase + 0 * GTILE + soff, Ahi + aoff, 16);
            cp_async16(bufbase + 1 * GTILE + soff, Alo + aoff, 16);
            const size_t boff = (size_t)(bn + row) * K + k0 + seg * 8;
            cp_async16(bufbase + 2 * GTILE + soff, Bhi + boff, 16);
            cp_async16(bufbase + 3 * GTILE + soff, Blo + boff, 16);
        }
        cp_commit();
    };

    load_chunk(0, sb);

    for (int c = 0; c < NC; c++) {
        const uint32_t bufbase = sb + (c & 1) * GBUF;
        if (c + 1 < NC) {
            load_chunk(c + 1, sb + ((c + 1) & 1) * GBUF);
            cp_wait1();
        } else {
            cp_wait0();
        }
        __syncthreads();

        const uint32_t sA_hi = bufbase + 0 * GTILE;
        const uint32_t sA_lo = bufbase + 1 * GTILE;
        const uint32_t sB_hi = bufbase + 2 * GTILE;
        const uint32_t sB_lo = bufbase + 3 * GTILE;

#pragma unroll
        for (int ks = 0; ks < 2; ks++) {
            const int kc = ks * 16;
            uint32_t ah[2][4], al[2][4];
#pragma unroll
            for (int mt = 0; mt < 2; mt++) {
                const int row = warp_m * 32 + mt * 16 + (lane & 15);
                const int col = kc + ((lane >> 4) << 3);
                const uint32_t off = row * GSTRIDE + col * 2;
                ldsm_x4(ah[mt], sA_hi + off);
                ldsm_x4(al[mt], sA_lo + off);
            }
#pragma unroll
            for (int half = 0; half < 2; half++) {
                uint32_t bh[4][2], bl[4][2];
#pragma unroll
                for (int bt = 0; bt < 2; bt++) {
                    const int nrow = warp_n * 64 + half * 32 + bt * 16
                                   + (lane & 7) + ((lane >> 4) & 1) * 8;
                    const int col  = kc + ((lane >> 3) & 1) * 8;
                    const uint32_t off = nrow * GSTRIDE + col * 2;
                    uint32_t t[4];
                    ldsm_x4(t, sB_hi + off);
                    bh[bt * 2][0] = t[0]; bh[bt * 2][1] = t[1];
                    bh[bt * 2 + 1][0] = t[2]; bh[bt * 2 + 1][1] = t[3];
                    ldsm_x4(t, sB_lo + off);
                    bl[bt * 2][0] = t[0]; bl[bt * 2][1] = t[1];
                    bl[bt * 2 + 1][0] = t[2]; bl[bt * 2 + 1][1] = t[3];
                }
#pragma unroll
                for (int mt = 0; mt < 2; mt++)
#pragma unroll
                    for (int j = 0; j < 4; j++) {
                        float* a = acc[mt][half * 4 + j];
                        mma_bf16(a, ah[mt], bh[j]);
                        mma_bf16(a, ah[mt], bl[j]);
                        mma_bf16(a, al[mt], bh[j]);
                    }
            }
        }
        __syncthreads();
    }

    const int cb = bn + warp_n * 64 + (lane & 3) * 2;
#pragma unroll
    for (int mt = 0; mt < 2; mt++) {
        const int row0 = bm + warp_m * 32 + mt * 16 + (lane >> 2);
#pragma unroll
        for (int h = 0; h < 2; h++) {
            const int row = row0 + h * 8;
            float* dst = C + (size_t)row * N + cb;
#pragma unroll
            for (int nt = 0; nt < 8; nt++) {
                float v0 = acc[mt][nt][h * 2 + 0];
                float v1 = acc[mt][nt][h * 2 + 1];
                v0 = 1.f / (1.f + expf(-v0));
                v1 = 1.f / (1.f + expf(-v1));
                *reinterpret_cast<float2*>(dst + nt * 8) = make_float2(v0, v1);
            }
        }
    }
}

// ---------------- SpMM layer 1 (fp16 gather): h_fp16 = relu(A @ s1 + b1) ----------------
__global__ __launch_bounds__(256) void spmm_relu_kernel(
    const int* __restrict__ col, const float* __restrict__ val,
    const float* __restrict__ bias)
{
    const int r  = blockIdx.x * 8 + (threadIdx.x >> 5);
    const int f8 = threadIdx.x & 31;
    const uint4* __restrict__ X4 = reinterpret_cast<const uint4*>(g_s1h);

    const int e0 = g_rowptr[r];
    const int e1 = g_rowptr[r + 1];

    float acc[8];
#pragma unroll
    for (int i = 0; i < 8; i++) acc[i] = 0.f;

    int e = e0;
    for (; e + 4 <= e1; e += 4) {
        int   c_[4]; float w_[4];
#pragma unroll
        for (int i = 0; i < 4; i++) { c_[i] = __ldg(&col[e + i]); w_[i] = __ldg(&val[e + i]); }
        uint4 q[4];
#pragma unroll
        for (int i = 0; i < 4; i++) q[i] = X4[(size_t)c_[i] * 32 + f8];
#pragma unroll
        for (int i = 0; i < 4; i++) {
            const __half2* h2 = reinterpret_cast<const __half2*>(&q[i]);
#pragma unroll
            for (int j = 0; j < 4; j++) {
                float2 f = __half22float2(h2[j]);
                acc[j * 2 + 0] = fmaf(w_[i], f.x, acc[j * 2 + 0]);
                acc[j * 2 + 1] = fmaf(w_[i], f.y, acc[j * 2 + 1]);
            }
        }
    }
    for (; e < e1; e++) {
        const int   c0 = __ldg(&col[e]);
        const float w0 = __ldg(&val[e]);
        uint4 q = X4[(size_t)c0 * 32 + f8];
        const __half2* h2 = reinterpret_cast<const __half2*>(&q);
#pragma unroll
        for (int j = 0; j < 4; j++) {
            float2 f = __half22float2(h2[j]);
            acc[j * 2 + 0] = fmaf(w0, f.x, acc[j * 2 + 0]);
            acc[j * 2 + 1] = fmaf(w0, f.y, acc[j * 2 + 1]);
        }
    }

    const float4 b0 = reinterpret_cast<const float4*>(bias)[f8 * 2 + 0];
    const float4 b1 = reinterpret_cast<const float4*>(bias)[f8 * 2 + 1];
    float y[8];
    y[0] = fmaxf(acc[0] + b0.x, 0.f); y[1] = fmaxf(acc[1] + b0.y, 0.f);
    y[2] = fmaxf(acc[2] + b0.z, 0.f); y[3] = fmaxf(acc[3] + b0.w, 0.f);
    y[4] = fmaxf(acc[4] + b1.x, 0.f); y[5] = fmaxf(acc[5] + b1.y, 0.f);
    y[6] = fmaxf(acc[6] + b1.z, 0.f); y[7] = fmaxf(acc[7] + b1.w, 0.f);

    union { uint4 u; __half2 h[4]; } H;
#pragma unroll
    for (int j = 0; j < 4; j++)
        H.h[j] = __floats2half2_rn(y[j * 2 + 0], y[j * 2 + 1]);
    reinterpret_cast<uint4*>(g_hf)[(size_t)r * 32 + f8] = H.u;
}

// ---------------- fused z-row + edge embedding for u/v only (coalesced WeT) ----------------
__global__ __launch_bounds__(NCLASS) void zuv_kernel(
    const int* __restrict__ u, const int* __restrict__ v,
    const int* __restrict__ col, const float* __restrict__ val,
    const float* __restrict__ b2)
{
    const bool is_u = blockIdx.x < N_UV;
    const int b = is_u ? blockIdx.x : blockIdx.x - N_UV;
    const int r = is_u ? __ldg(&u[b]) : __ldg(&v[b]);
    const int t = threadIdx.x;            // 0..127

    const int e0 = g_rowptr[r];
    const int e1 = g_rowptr[r + 1];
    float acc[4];
#pragma unroll
    for (int i = 0; i < 4; i++) acc[i] = 0.f;
    int e = e0;
    for (; e + 4 <= e1; e += 4) {
#pragma unroll
        for (int i = 0; i < 4; i++) {
            const int   c0 = __ldg(&col[e + i]);
            const float w0 = __ldg(&val[e + i]);
            acc[i] = fmaf(w0, __half2float(g_s2h[(size_t)c0 * NCLASS + t]), acc[i]);
        }
    }
    for (; e < e1; e++) {
        acc[0] = fmaf(__ldg(&val[e]),
                      __half2float(g_s2h[(size_t)__ldg(&col[e]) * NCLASS + t]), acc[0]);
    }
    const float zt = acc[0] + acc[1] + acc[2] + acc[3] + __ldg(&b2[t]);

    __nv_bfloat16 h, l;
    if (is_u) {
        __shared__ float zrow[NCLASS];
        zrow[t] = zt;
        __syncthreads();
        float s = 0.f;
        // coalesced: lane t reads WeT[k*NCLASS + t] (consecutive addresses across lanes)
#pragma unroll 8
        for (int k = 0; k < NCLASS; k++)
            s = fmaf(zrow[k], __ldg(&g_weT[(size_t)k * NCLASS + t]), s);
        split_f32(s, h, l);
        g_zuhi[(size_t)b * NCLASS + t] = h;
        g_zulo[(size_t)b * NCLASS + t] = l;
    } else {
        split_f32(zt, h, l);
        g_zvhi[(size_t)b * NCLASS + t] = h;
        g_zvlo[(size_t)b * NCLASS + t] = l;
    }
}

// ---------------- launch ----------------
extern "C" void kernel_launch(void* const* d_in, const int* in_sizes, int n_in,
                              void* d_out, int out_size)
{
    const int*   u       = (const int*)d_in[0];
    const int*   v       = (const int*)d_in[1];
    const float* x       = (const float*)d_in[2];
    const int*   adj_row = (const int*)d_in[3];
    const int*   adj_col = (const int*)d_in[4];
    const float* adj_val = (const float*)d_in[5];
    const float* W1      = (const float*)d_in[6];
    const float* b1      = (const float*)d_in[7];
    const float* W2      = (const float*)d_in[8];
    const float* b2      = (const float*)d_in[9];
    const float* We      = (const float*)d_in[10];
    float* out = (float*)d_out;

    __nv_bfloat16 *w1th, *w1tl, *zuh, *zul, *zvh, *zvl;
    __half *s1h, *hf, *w2th, *w2tl, *s2h;
    cudaGetSymbolAddress((void**)&w1th, g_w1t_hi);
    cudaGetSymbolAddress((void**)&w1tl, g_w1t_lo);
    cudaGetSymbolAddress((void**)&s1h, g_s1h);
    cudaGetSymbolAddress((void**)&hf,  g_hf);
    cudaGetSymbolAddress((void**)&w2th, g_w2t_hi);
    cudaGetSymbolAddress((void**)&w2tl, g_w2t_lo);
    cudaGetSymbolAddress((void**)&s2h, g_s2h);
    cudaGetSymbolAddress((void**)&zuh, g_zuhi);
    cudaGetSymbolAddress((void**)&zul, g_zulo);
    cudaGetSymbolAddress((void**)&zvh, g_zvhi);
    cudaGetSymbolAddress((void**)&zvl, g_zvlo);

    const int SMEM4 = 2 * GBUF;    // 81920
    const int SMEM3 = 2 * GBUF3;   // 61440
    cudaFuncSetAttribute(mma_gemm_kernel, cudaFuncAttributeMaxDynamicSharedMemorySize, SMEM4);
    cudaFuncSetAttribute(mma_gemm_f32a_kernel, cudaFuncAttributeMaxDynamicSharedMemorySize, SMEM4);
    cudaFuncSetAttribute(mma_gemm_f16a_kernel, cudaFuncAttributeMaxDynamicSharedMemorySize, SMEM3);

    // 1. prep: weight transpose/split + We^T + rowptr
    prep_kernel<<<NB_W + NB_WE + NB_ROW, 256>>>(W1, W2, We, adj_row);

    // 2. support1 = x @ W1  (fp32 A on-the-fly bf16x3, fp16 output)
    {
        dim3 grid(NHID / 128, (N_NODES + 127) / 128);
        mma_gemm_f32a_kernel<<<grid, 256, SMEM4>>>(x, w1th, w1tl, s1h,
                                                   N_NODES, NHID, NFEAT);
    }

    // 3. h = relu(A @ s1 + b1), fp16 gather, fp16 output
    spmm_relu_kernel<<<N_NODES / 8, 256>>>(adj_col, adj_val, b1);

    // 4. support2 = h @ W2   (fp16 HMMA, W2 fp16 hi/lo, fp16 output)
    {
        dim3 grid(NCLASS / 128, (N_NODES + 127) / 128);
        mma_gemm_f16a_kernel<<<grid, 256, SMEM3>>>(hf, w2th, w2tl, s2h,
                                                   N_NODES, NCLASS, NHID);
    }

    // 5. fused: z-rows for u/v only, + coalesced WeT rotation + bf16 split
    zuv_kernel<<<2 * N_UV, NCLASS>>>(u, v, adj_col, adj_val, b2);

    // 6. out = sigmoid(zu @ zv^T)  (bf16x3, fused sigmoid)
    {
        dim3 grid(N_UV / 128, N_UV / 128);
        mma_gemm_kernel<<<grid, 256, SMEM4>>>(zuh, zul, zvh, zvl, out,
                                              N_UV, N_UV, NCLASS);
    }
}

// round 15
// speedup vs baseline: 2.1387x; 1.1620x over previous
#include <cuda_runtime.h>
#include <cuda_bf16.h>
#include <cuda_fp16.h>
#include <math.h>
#include <cstdint>

#define N_NODES 50000
#define N_EDGES 800000
#define NFEAT   512
#define NHID    256
#define NCLASS  128
#define N_UV    2048

// ---------------- scratch (device globals; no allocation allowed) ----------------
__device__ __half        g_w1t_hi[NHID * NFEAT];    // W1^T fp16 hi
__device__ __half        g_w1t_lo[NHID * NFEAT];    // W1^T fp16 lo
__device__ __half        g_s1h[N_NODES * NHID];     // support1 fp16
__device__ __half        g_hf[N_NODES * NHID];      // h fp16
__device__ __half        g_w2t_hi[NCLASS * NHID];   // W2^T fp16 hi
__device__ __half        g_w2t_lo[NCLASS * NHID];   // W2^T fp16 lo
__device__ __half        g_s2h[N_NODES * NCLASS];   // support2 fp16
__device__ float         g_weT[NCLASS * NCLASS];    // We^T (coalesced access in zuv)
__device__ __nv_bfloat16 g_zuhi[N_UV * NCLASS];
__device__ __nv_bfloat16 g_zulo[N_UV * NCLASS];
__device__ __nv_bfloat16 g_zvhi[N_UV * NCLASS];
__device__ __nv_bfloat16 g_zvlo[N_UV * NCLASS];
__device__ int           g_rowptr[N_NODES + 1];

// ---------------- helpers ----------------
__device__ __forceinline__ uint32_t smem_to_u32(const void* p) {
    uint32_t a;
    asm("{ .reg .u64 t; cvta.to.shared.u64 t, %1; cvt.u32.u64 %0, t; }" : "=r"(a) : "l"(p));
    return a;
}

__device__ __forceinline__ void ldsm_x4(uint32_t* r, uint32_t addr) {
    asm volatile("ldmatrix.sync.aligned.m8n8.x4.shared.b16 {%0,%1,%2,%3}, [%4];"
                 : "=r"(r[0]), "=r"(r[1]), "=r"(r[2]), "=r"(r[3]) : "r"(addr));
}

__device__ __forceinline__ void mma_bf16(float* d, const uint32_t* a, const uint32_t* b) {
    asm volatile(
        "mma.sync.aligned.m16n8k16.row.col.f32.bf16.bf16.f32 "
        "{%0,%1,%2,%3}, {%4,%5,%6,%7}, {%8,%9}, {%0,%1,%2,%3};\n"
        : "+f"(d[0]), "+f"(d[1]), "+f"(d[2]), "+f"(d[3])
        : "r"(a[0]), "r"(a[1]), "r"(a[2]), "r"(a[3]), "r"(b[0]), "r"(b[1]));
}

__device__ __forceinline__ void mma_f16(float* d, const uint32_t* a, const uint32_t* b) {
    asm volatile(
        "mma.sync.aligned.m16n8k16.row.col.f32.f16.f16.f32 "
        "{%0,%1,%2,%3}, {%4,%5,%6,%7}, {%8,%9}, {%0,%1,%2,%3};\n"
        : "+f"(d[0]), "+f"(d[1]), "+f"(d[2]), "+f"(d[3])
        : "r"(a[0]), "r"(a[1]), "r"(a[2]), "r"(a[3]), "r"(b[0]), "r"(b[1]));
}

__device__ __forceinline__ void cp_async16(uint32_t dst, const void* src, int src_bytes) {
    asm volatile("cp.async.cg.shared.global [%0], [%1], 16, %2;"
                 :: "r"(dst), "l"(src), "r"(src_bytes) : "memory");
}
__device__ __forceinline__ void cp_commit() {
    asm volatile("cp.async.commit_group;" ::: "memory");
}
__device__ __forceinline__ void cp_wait1() {
    asm volatile("cp.async.wait_group 1;" ::: "memory");
}
__device__ __forceinline__ void cp_wait0() {
    asm volatile("cp.async.wait_group 0;" ::: "memory");
}

__device__ __forceinline__ void split_f32(float v, __nv_bfloat16& hi, __nv_bfloat16& lo) {
    hi = __float2bfloat16_rn(v);
    lo = __float2bfloat16_rn(v - __bfloat162float(hi));
}

__device__ __forceinline__ void split_f32h(float v, __half& hi, __half& lo) {
    hi = __float2half_rn(v);
    lo = __float2half_rn(v - __half2float(hi));
}

__device__ __forceinline__ void sts64(uint32_t addr, uint32_t a, uint32_t b) {
    asm volatile("st.shared.v2.b32 [%0], {%1, %2};" :: "r"(addr), "r"(a), "r"(b) : "memory");
}

// ---------------- prep: W1 fp16 split (T), W2 fp16 split (T), We^T, rowptr ----------------
#define NB_W     (((NFEAT * NHID + NHID * NCLASS) + 255) / 256)        // 640
#define NB_WE    ((NCLASS * NCLASS) / 256)                             // 64
#define NB_ROW   ((N_NODES + 1 + 255) / 256)                           // 196

__global__ __launch_bounds__(256) void prep_kernel(
    const float* __restrict__ W1, const float* __restrict__ W2,
    const float* __restrict__ We, const int* __restrict__ adj_row)
{
    const int bid = blockIdx.x;
    if (bid < NB_W) {
        int i = bid * 256 + threadIdx.x;
        if (i < NFEAT * NHID) {
            int k = i / NHID, n = i % NHID;
            __half h, l;
            split_f32h(W1[i], h, l);
            g_w1t_hi[(size_t)n * NFEAT + k] = h;
            g_w1t_lo[(size_t)n * NFEAT + k] = l;
        } else {
            int j = i - NFEAT * NHID;
            if (j < NHID * NCLASS) {
                int k = j / NCLASS, n = j % NCLASS;
                __half h, l;
                split_f32h(W2[j], h, l);
                g_w2t_hi[(size_t)n * NHID + k] = h;
                g_w2t_lo[(size_t)n * NHID + k] = l;
            }
        }
    } else if (bid < NB_W + NB_WE) {
        int i = (bid - NB_W) * 256 + threadIdx.x;    // i = t*NCLASS + k
        int t = i / NCLASS, k = i % NCLASS;
        g_weT[(size_t)k * NCLASS + t] = We[i];
    } else {
        int i = (bid - NB_W - NB_WE) * 256 + threadIdx.x;
        if (i > N_NODES) return;
        int lo = 0, hi = N_EDGES;
        while (lo < hi) {
            int mid = (lo + hi) >> 1;
            if (adj_row[mid] < i) lo = mid + 1; else hi = mid;
        }
        g_rowptr[i] = lo;
    }
}

// ---------------- common tile constants ----------------
#define GSTRIDE 80                     // smem row stride in bytes (40 x 16-bit)
#define GTILE   (128 * GSTRIDE)        // 10240 bytes per operand tile
#define GBUF    (4 * GTILE)            // 4-tile buffer (bf16x3 GEMM3)
#define GBUF3   (3 * GTILE)            // 3-tile buffer (fp16 A-single kernels)

// ---------------- GEMM1: C_fp16[M,N] = A_fp32 @ B^T, A converted to fp16 on the fly ----------------
__global__ __launch_bounds__(256, 2) void mma_gemm_f32a_kernel(
    const float* __restrict__ A,
    const __half* __restrict__ Bhi, const __half* __restrict__ Blo,
    __half* __restrict__ C, int M, int N, int K)
{
    extern __shared__ char smem_raw[];
    const uint32_t sb = smem_to_u32(smem_raw);

    const int tid  = threadIdx.x;
    const int wid  = tid >> 5;
    const int lane = tid & 31;
    const int warp_m = wid & 3;
    const int warp_n = wid >> 2;
    const int bm = blockIdx.y * 128;
    const int bn = blockIdx.x * 128;

    float acc[2][8][4];
#pragma unroll
    for (int mt = 0; mt < 2; mt++)
#pragma unroll
        for (int nt = 0; nt < 8; nt++)
#pragma unroll
            for (int i = 0; i < 4; i++) acc[mt][nt][i] = 0.f;

    const int NC = K >> 5;

    float4 pa[4];
    auto ldgA = [&](int c) {
        const int k0 = c << 5;
#pragma unroll
        for (int i = 0; i < 4; i++) {
            const int s = tid + i * 256;
            const int row = s >> 3;
            const int seg = s & 7;
            const int ar = bm + row;
            if (ar < M)
                pa[i] = *reinterpret_cast<const float4*>(A + (size_t)ar * K + k0 + seg * 4);
            else
                pa[i] = make_float4(0.f, 0.f, 0.f, 0.f);
        }
    };
    auto stsA = [&](uint32_t bufbase) {
#pragma unroll
        for (int i = 0; i < 4; i++) {
            const int s = tid + i * 256;
            const int row = s >> 3;
            const int seg = s & 7;
            union { __half2 h2[2]; uint32_t u[2]; } H;
            H.h2[0] = __floats2half2_rn(pa[i].x, pa[i].y);
            H.h2[1] = __floats2half2_rn(pa[i].z, pa[i].w);
            sts64(bufbase + row * GSTRIDE + seg * 8, H.u[0], H.u[1]);
        }
    };
    auto ldB = [&](int c, uint32_t bufbase) {
        const int k0 = c << 5;
#pragma unroll
        for (int i = 0; i < 2; i++) {
            const int s = tid + i * 256;
            const int row = s >> 2;
            const int seg = s & 3;
            const uint32_t soff = row * GSTRIDE + seg * 16;
            const size_t boff = (size_t)(bn + row) * K + k0 + seg * 8;
            cp_async16(bufbase + 1 * GTILE + soff, Bhi + boff, 16);
            cp_async16(bufbase + 2 * GTILE + soff, Blo + boff, 16);
        }
        cp_commit();
    };

    ldgA(0);
    ldB(0, sb);

    for (int c = 0; c < NC; c++) {
        const uint32_t bufbase = sb + (c & 1) * GBUF3;
        stsA(bufbase);
        if (c + 1 < NC) {
            ldgA(c + 1);
            ldB(c + 1, sb + ((c + 1) & 1) * GBUF3);
            cp_wait1();
        } else {
            cp_wait0();
        }
        __syncthreads();

        const uint32_t sA    = bufbase;
        const uint32_t sB_hi = bufbase + 1 * GTILE;
        const uint32_t sB_lo = bufbase + 2 * GTILE;

#pragma unroll
        for (int ks = 0; ks < 2; ks++) {
            const int kc = ks * 16;
            uint32_t ah[2][4];
#pragma unroll
            for (int mt = 0; mt < 2; mt++) {
                const int row = warp_m * 32 + mt * 16 + (lane & 15);
                const int col = kc + ((lane >> 4) << 3);
                ldsm_x4(ah[mt], sA + row * GSTRIDE + col * 2);
            }
#pragma unroll
            for (int half = 0; half < 2; half++) {
                uint32_t bh[4][2], bl[4][2];
#pragma unroll
                for (int bt = 0; bt < 2; bt++) {
                    const int nrow = warp_n * 64 + half * 32 + bt * 16
                                   + (lane & 7) + ((lane >> 4) & 1) * 8;
                    const int col  = kc + ((lane >> 3) & 1) * 8;
                    const uint32_t off = nrow * GSTRIDE + col * 2;
                    uint32_t t[4];
                    ldsm_x4(t, sB_hi + off);
                    bh[bt * 2][0] = t[0]; bh[bt * 2][1] = t[1];
                    bh[bt * 2 + 1][0] = t[2]; bh[bt * 2 + 1][1] = t[3];
                    ldsm_x4(t, sB_lo + off);
                    bl[bt * 2][0] = t[0]; bl[bt * 2][1] = t[1];
                    bl[bt * 2 + 1][0] = t[2]; bl[bt * 2 + 1][1] = t[3];
                }
#pragma unroll
                for (int mt = 0; mt < 2; mt++)
#pragma unroll
                    for (int j = 0; j < 4; j++) {
                        float* a = acc[mt][half * 4 + j];
                        mma_f16(a, ah[mt], bh[j]);
                        mma_f16(a, ah[mt], bl[j]);
                    }
            }
        }
        __syncthreads();
    }

    const int cb = bn + warp_n * 64 + (lane & 3) * 2;
#pragma unroll
    for (int mt = 0; mt < 2; mt++) {
        const int row0 = bm + warp_m * 32 + mt * 16 + (lane >> 2);
#pragma unroll
        for (int h = 0; h < 2; h++) {
            const int row = row0 + h * 8;
            if (row >= M) continue;
            __half* dst = C + (size_t)row * N + cb;
#pragma unroll
            for (int nt = 0; nt < 8; nt++) {
                *reinterpret_cast<__half2*>(dst + nt * 8) =
                    __floats2half2_rn(acc[mt][nt][h * 2 + 0], acc[mt][nt][h * 2 + 1]);
            }
        }
    }
}

// ---------------- GEMM2: C_fp16[M,N] = A_fp16 @ (Bhi+Blo)^T, fp16 HMMA (2 MMAs) ----------------
__global__ __launch_bounds__(256, 2) void mma_gemm_f16a_kernel(
    const __half* __restrict__ A,
    const __half* __restrict__ Bhi, const __half* __restrict__ Blo,
    __half* __restrict__ C, int M, int N, int K)
{
    extern __shared__ char smem_raw[];
    const uint32_t sb = smem_to_u32(smem_raw);

    const int tid  = threadIdx.x;
    const int wid  = tid >> 5;
    const int lane = tid & 31;
    const int warp_m = wid & 3;
    const int warp_n = wid >> 2;
    const int bm = blockIdx.y * 128;
    const int bn = blockIdx.x * 128;

    float acc[2][8][4];
#pragma unroll
    for (int mt = 0; mt < 2; mt++)
#pragma unroll
        for (int nt = 0; nt < 8; nt++)
#pragma unroll
            for (int i = 0; i < 4; i++) acc[mt][nt][i] = 0.f;

    const int NC = K >> 5;

    auto load_chunk = [&](int c, uint32_t bufbase) {
        const int k0 = c << 5;
#pragma unroll
        for (int i = 0; i < 2; i++) {
            const int s = tid + i * 256;
            const int row = s >> 2;
            const int seg = s & 3;
            const uint32_t soff = row * GSTRIDE + seg * 16;
            const int ar = bm + row;
            const int okA = (ar < M) ? 16 : 0;
            const int arc = okA ? ar : 0;
            cp_async16(bufbase + soff, A + (size_t)arc * K + k0 + seg * 8, okA);
            const size_t boff = (size_t)(bn + row) * K + k0 + seg * 8;
            cp_async16(bufbase + 1 * GTILE + soff, Bhi + boff, 16);
            cp_async16(bufbase + 2 * GTILE + soff, Blo + boff, 16);
        }
        cp_commit();
    };

    load_chunk(0, sb);

    for (int c = 0; c < NC; c++) {
        const uint32_t bufbase = sb + (c & 1) * GBUF3;
        if (c + 1 < NC) {
            load_chunk(c + 1, sb + ((c + 1) & 1) * GBUF3);
            cp_wait1();
        } else {
            cp_wait0();
        }
        __syncthreads();

        const uint32_t sA   = bufbase;
        const uint32_t sB_hi = bufbase + 1 * GTILE;
        const uint32_t sB_lo = bufbase + 2 * GTILE;

#pragma unroll
        for (int ks = 0; ks < 2; ks++) {
            const int kc = ks * 16;
            uint32_t ah[2][4];
#pragma unroll
            for (int mt = 0; mt < 2; mt++) {
                const int row = warp_m * 32 + mt * 16 + (lane & 15);
                const int col = kc + ((lane >> 4) << 3);
                ldsm_x4(ah[mt], sA + row * GSTRIDE + col * 2);
            }
#pragma unroll
            for (int half = 0; half < 2; half++) {
                uint32_t bh[4][2], bl[4][2];
#pragma unroll
                for (int bt = 0; bt < 2; bt++) {
                    const int nrow = warp_n * 64 + half * 32 + bt * 16
                                   + (lane & 7) + ((lane >> 4) & 1) * 8;
                    const int col  = kc + ((lane >> 3) & 1) * 8;
                    const uint32_t off = nrow * GSTRIDE + col * 2;
                    uint32_t t[4];
                    ldsm_x4(t, sB_hi + off);
                    bh[bt * 2][0] = t[0]; bh[bt * 2][1] = t[1];
                    bh[bt * 2 + 1][0] = t[2]; bh[bt * 2 + 1][1] = t[3];
                    ldsm_x4(t, sB_lo + off);
                    bl[bt * 2][0] = t[0]; bl[bt * 2][1] = t[1];
                    bl[bt * 2 + 1][0] = t[2]; bl[bt * 2 + 1][1] = t[3];
                }
#pragma unroll
                for (int mt = 0; mt < 2; mt++)
#pragma unroll
                    for (int j = 0; j < 4; j++) {
                        float* a = acc[mt][half * 4 + j];
                        mma_f16(a, ah[mt], bh[j]);
                        mma_f16(a, ah[mt], bl[j]);
                    }
            }
        }
        __syncthreads();
    }

    const int cb = bn + warp_n * 64 + (lane & 3) * 2;
#pragma unroll
    for (int mt = 0; mt < 2; mt++) {
        const int row0 = bm + warp_m * 32 + mt * 16 + (lane >> 2);
#pragma unroll
        for (int h = 0; h < 2; h++) {
            const int row = row0 + h * 8;
            if (row >= M) continue;
            __half* dst = C + (size_t)row * N + cb;
#pragma unroll
            for (int nt = 0; nt < 8; nt++) {
                *reinterpret_cast<__half2*>(dst + nt * 8) =
                    __floats2half2_rn(acc[mt][nt][h * 2 + 0], acc[mt][nt][h * 2 + 1]);
            }
        }
    }
}

// ---------------- GEMM3: sigmoid(A @ B^T), bf16x3, fp32 out ----------------
__global__ __launch_bounds__(256, 2) void mma_gemm_kernel(
    const __nv_bfloat16* __restrict__ Ahi, const __nv_bfloat16* __restrict__ Alo,
    const __nv_bfloat16* __restrict__ Bhi, const __nv_bfloat16* __restrict__ Blo,
    float* __restrict__ C, int M, int N, int K)
{
    extern __shared__ char smem_raw[];
    const uint32_t sb = smem_to_u32(smem_raw);

    const int tid  = threadIdx.x;
    const int wid  = tid >> 5;
    const int lane = tid & 31;
    const int warp_m = wid & 3;
    const int warp_n = wid >> 2;
    const int bm = blockIdx.y * 128;
    const int bn = blockIdx.x * 128;

    float acc[2][8][4];
#pragma unroll
    for (int mt = 0; mt < 2; mt++)
#pragma unroll
        for (int nt = 0; nt < 8; nt++)
#pragma unroll
            for (int i = 0; i < 4; i++) acc[mt][nt][i] = 0.f;

    const int NC = K >> 5;

    auto load_chunk = [&](int c, uint32_t bufbase) {
        const int k0 = c << 5;
#pragma unroll
        for (int i = 0; i < 2; i++) {
            const int s = tid + i * 256;
            const int row = s >> 2;
            const int seg = s & 3;
            const uint32_t soff = row * GSTRIDE + seg * 16;
            const size_t aoff = (size_t)(bm + row) * K + k0 + seg * 8;
            cp_async16(bufbase + 0 * GTILE + soff, Ahi + aoff, 16);
            cp_async16(bufbase + 1 * GTILE + soff, Alo + aoff, 16);
            const size_t boff = (size_t)(bn + row) * K + k0 + seg * 8;
            cp_async16(bufbase + 2 * GTILE + soff, Bhi + boff, 16);
            cp_async16(bufbase + 3 * GTILE + soff, Blo + boff, 16);
        }
        cp_commit();
    };

    load_chunk(0, sb);

    for (int c = 0; c < NC; c++) {
        const uint32_t bufbase = sb + (c & 1) * GBUF;
        if (c + 1 < NC) {
            load_chunk(c + 1, sb + ((c + 1) & 1) * GBUF);
            cp_wait1();
        } else {
            cp_wait0();
        }
        __syncthreads();

        const uint32_t sA_hi = bufbase + 0 * GTILE;
        const uint32_t sA_lo = bufbase + 1 * GTILE;
        const uint32_t sB_hi = bufbase + 2 * GTILE;
        const uint32_t sB_lo = bufbase + 3 * GTILE;

#pragma unroll
        for (int ks = 0; ks < 2; ks++) {
            const int kc = ks * 16;
            uint32_t ah[2][4], al[2][4];
#pragma unroll
            for (int mt = 0; mt < 2; mt++) {
                const int row = warp_m * 32 + mt * 16 + (lane & 15);
                const int col = kc + ((lane >> 4) << 3);
                const uint32_t off = row * GSTRIDE + col * 2;
                ldsm_x4(ah[mt], sA_hi + off);
                ldsm_x4(al[mt], sA_lo + off);
            }
#pragma unroll
            for (int half = 0; half < 2; half++) {
                uint32_t bh[4][2], bl[4][2];
#pragma unroll
                for (int bt = 0; bt < 2; bt++) {
                    const int nrow = warp_n * 64 + half * 32 + bt * 16
                                   + (lane & 7) + ((lane >> 4) & 1) * 8;
                    const int col  = kc + ((lane >> 3) & 1) * 8;
                    const uint32_t off = nrow * GSTRIDE + col * 2;
                    uint32_t t[4];
                    ldsm_x4(t, sB_hi + off);
                    bh[bt * 2][0] = t[0]; bh[bt * 2][1] = t[1];
                    bh[bt * 2 + 1][0] = t[2]; bh[bt * 2 + 1][1] = t[3];
                    ldsm_x4(t, sB_lo + off);
                    bl[bt * 2][0] = t[0]; bl[bt * 2][1] = t[1];
                    bl[bt * 2 + 1][0] = t[2]; bl[bt * 2 + 1][1] = t[3];
                }
#pragma unroll
                for (int mt = 0; mt < 2; mt++)
#pragma unroll
                    for (int j = 0; j < 4; j++) {
                        float* a = acc[mt][half * 4 + j];
                        mma_bf16(a, ah[mt], bh[j]);
                        mma_bf16(a, ah[mt], bl[j]);
                        mma_bf16(a, al[mt], bh[j]);
                    }
            }
        }
        __syncthreads();
    }

    const int cb = bn + warp_n * 64 + (lane & 3) * 2;
#pragma unroll
    for (int mt = 0; mt < 2; mt++) {
        const int row0 = bm + warp_m * 32 + mt * 16 + (lane >> 2);
#pragma unroll
        for (int h = 0; h < 2; h++) {
            const int row = row0 + h * 8;
            float* dst = C + (size_t)row * N + cb;
#pragma unroll
            for (int nt = 0; nt < 8; nt++) {
                float v0 = acc[mt][nt][h * 2 + 0];
                float v1 = acc[mt][nt][h * 2 + 1];
                v0 = 1.f / (1.f + expf(-v0));
                v1 = 1.f / (1.f + expf(-v1));
                *reinterpret_cast<float2*>(dst + nt * 8) = make_float2(v0, v1);
            }
        }
    }
}

// ---------------- SpMM layer 1 (fp16 gather): h_fp16 = relu(A @ s1 + b1) ----------------
__global__ __launch_bounds__(256) void spmm_relu_kernel(
    const int* __restrict__ col, const float* __restrict__ val,
    const float* __restrict__ bias)
{
    const int r  = blockIdx.x * 8 + (threadIdx.x >> 5);
    const int f8 = threadIdx.x & 31;
    const uint4* __restrict__ X4 = reinterpret_cast<const uint4*>(g_s1h);

    const int e0 = g_rowptr[r];
    const int e1 = g_rowptr[r + 1];

    float acc[8];
#pragma unroll
    for (int i = 0; i < 8; i++) acc[i] = 0.f;

    int e = e0;
    for (; e + 4 <= e1; e += 4) {
        int   c_[4]; float w_[4];
#pragma unroll
        for (int i = 0; i < 4; i++) { c_[i] = __ldg(&col[e + i]); w_[i] = __ldg(&val[e + i]); }
        uint4 q[4];
#pragma unroll
        for (int i = 0; i < 4; i++) q[i] = X4[(size_t)c_[i] * 32 + f8];
#pragma unroll
        for (int i = 0; i < 4; i++) {
            const __half2* h2 = reinterpret_cast<const __half2*>(&q[i]);
#pragma unroll
            for (int j = 0; j < 4; j++) {
                float2 f = __half22float2(h2[j]);
                acc[j * 2 + 0] = fmaf(w_[i], f.x, acc[j * 2 + 0]);
                acc[j * 2 + 1] = fmaf(w_[i], f.y, acc[j * 2 + 1]);
            }
        }
    }
    for (; e < e1; e++) {
        const int   c0 = __ldg(&col[e]);
        const float w0 = __ldg(&val[e]);
        uint4 q = X4[(size_t)c0 * 32 + f8];
        const __half2* h2 = reinterpret_cast<const __half2*>(&q);
#pragma unroll
        for (int j = 0; j < 4; j++) {
            float2 f = __half22float2(h2[j]);
            acc[j * 2 + 0] = fmaf(w0, f.x, acc[j * 2 + 0]);
            acc[j * 2 + 1] = fmaf(w0, f.y, acc[j * 2 + 1]);
        }
    }

    const float4 b0 = reinterpret_cast<const float4*>(bias)[f8 * 2 + 0];
    const float4 b1 = reinterpret_cast<const float4*>(bias)[f8 * 2 + 1];
    float y[8];
    y[0] = fmaxf(acc[0] + b0.x, 0.f); y[1] = fmaxf(acc[1] + b0.y, 0.f);
    y[2] = fmaxf(acc[2] + b0.z, 0.f); y[3] = fmaxf(acc[3] + b0.w, 0.f);
    y[4] = fmaxf(acc[4] + b1.x, 0.f); y[5] = fmaxf(acc[5] + b1.y, 0.f);
    y[6] = fmaxf(acc[6] + b1.z, 0.f); y[7] = fmaxf(acc[7] + b1.w, 0.f);

    union { uint4 u; __half2 h[4]; } H;
#pragma unroll
    for (int j = 0; j < 4; j++)
        H.h[j] = __floats2half2_rn(y[j * 2 + 0], y[j * 2 + 1]);
    reinterpret_cast<uint4*>(g_hf)[(size_t)r * 32 + f8] = H.u;
}

// ---------------- fused z-row + edge embedding for u/v only (coalesced WeT) ----------------
__global__ __launch_bounds__(NCLASS) void zuv_kernel(
    const int* __restrict__ u, const int* __restrict__ v,
    const int* __restrict__ col, const float* __restrict__ val,
    const float* __restrict__ b2)
{
    const bool is_u = blockIdx.x < N_UV;
    const int b = is_u ? blockIdx.x : blockIdx.x - N_UV;
    const int r = is_u ? __ldg(&u[b]) : __ldg(&v[b]);
    const int t = threadIdx.x;            // 0..127

    const int e0 = g_rowptr[r];
    const int e1 = g_rowptr[r + 1];
    float acc[4];
#pragma unroll
    for (int i = 0; i < 4; i++) acc[i] = 0.f;
    int e = e0;
    for (; e + 4 <= e1; e += 4) {
#pragma unroll
        for (int i = 0; i < 4; i++) {
            const int   c0 = __ldg(&col[e + i]);
            const float w0 = __ldg(&val[e + i]);
            acc[i] = fmaf(w0, __half2float(g_s2h[(size_t)c0 * NCLASS + t]), acc[i]);
        }
    }
    for (; e < e1; e++) {
        acc[0] = fmaf(__ldg(&val[e]),
                      __half2float(g_s2h[(size_t)__ldg(&col[e]) * NCLASS + t]), acc[0]);
    }
    const float zt = acc[0] + acc[1] + acc[2] + acc[3] + __ldg(&b2[t]);

    __nv_bfloat16 h, l;
    if (is_u) {
        __shared__ float zrow[NCLASS];
        zrow[t] = zt;
        __syncthreads();
        float s = 0.f;
#pragma unroll 8
        for (int k = 0; k < NCLASS; k++)
            s = fmaf(zrow[k], __ldg(&g_weT[(size_t)k * NCLASS + t]), s);
        split_f32(s, h, l);
        g_zuhi[(size_t)b * NCLASS + t] = h;
        g_zulo[(size_t)b * NCLASS + t] = l;
    } else {
        split_f32(zt, h, l);
        g_zvhi[(size_t)b * NCLASS + t] = h;
        g_zvlo[(size_t)b * NCLASS + t] = l;
    }
}

// ---------------- launch ----------------
extern "C" void kernel_launch(void* const* d_in, const int* in_sizes, int n_in,
                              void* d_out, int out_size)
{
    const int*   u       = (const int*)d_in[0];
    const int*   v       = (const int*)d_in[1];
    const float* x       = (const float*)d_in[2];
    const int*   adj_row = (const int*)d_in[3];
    const int*   adj_col = (const int*)d_in[4];
    const float* adj_val = (const float*)d_in[5];
    const float* W1      = (const float*)d_in[6];
    const float* b1      = (const float*)d_in[7];
    const float* W2      = (const float*)d_in[8];
    const float* b2      = (const float*)d_in[9];
    const float* We      = (const float*)d_in[10];
    float* out = (float*)d_out;

    __nv_bfloat16 *zuh, *zul, *zvh, *zvl;
    __half *w1th, *w1tl, *s1h, *hf, *w2th, *w2tl, *s2h;
    cudaGetSymbolAddress((void**)&w1th, g_w1t_hi);
    cudaGetSymbolAddress((void**)&w1tl, g_w1t_lo);
    cudaGetSymbolAddress((void**)&s1h, g_s1h);
    cudaGetSymbolAddress((void**)&hf,  g_hf);
    cudaGetSymbolAddress((void**)&w2th, g_w2t_hi);
    cudaGetSymbolAddress((void**)&w2tl, g_w2t_lo);
    cudaGetSymbolAddress((void**)&s2h, g_s2h);
    cudaGetSymbolAddress((void**)&zuh, g_zuhi);
    cudaGetSymbolAddress((void**)&zul, g_zulo);
    cudaGetSymbolAddress((void**)&zvh, g_zvhi);
    cudaGetSymbolAddress((void**)&zvl, g_zvlo);

    const int SMEM4 = 2 * GBUF;    // 81920
    const int SMEM3 = 2 * GBUF3;   // 61440
    cudaFuncSetAttribute(mma_gemm_kernel, cudaFuncAttributeMaxDynamicSharedMemorySize, SMEM4);
    cudaFuncSetAttribute(mma_gemm_f32a_kernel, cudaFuncAttributeMaxDynamicSharedMemorySize, SMEM3);
    cudaFuncSetAttribute(mma_gemm_f16a_kernel, cudaFuncAttributeMaxDynamicSharedMemorySize, SMEM3);

    // 1. prep: weight transpose/split + We^T + rowptr
    prep_kernel<<<NB_W + NB_WE + NB_ROW, 256>>>(W1, W2, We, adj_row);

    // 2. support1 = x @ W1  (fp32 A -> fp16 on the fly, W1 fp16 hi/lo, 2 MMAs)
    {
        dim3 grid(NHID / 128, (N_NODES + 127) / 128);
        mma_gemm_f32a_kernel<<<grid, 256, SMEM3>>>(x, w1th, w1tl, s1h,
                                                   N_NODES, NHID, NFEAT);
    }

    // 3. h = relu(A @ s1 + b1), fp16 gather, fp16 output
    spmm_relu_kernel<<<N_NODES / 8, 256>>>(adj_col, adj_val, b1);

    // 4. support2 = h @ W2   (fp16 HMMA, W2 fp16 hi/lo, fp16 output)
    {
        dim3 grid(NCLASS / 128, (N_NODES + 127) / 128);
        mma_gemm_f16a_kernel<<<grid, 256, SMEM3>>>(hf, w2th, w2tl, s2h,
                                                   N_NODES, NCLASS, NHID);
    }

    // 5. fused: z-rows for u/v only, + coalesced WeT rotation + bf16 split
    zuv_kernel<<<2 * N_UV, NCLASS>>>(u, v, adj_col, adj_val, b2);

    // 6. out = sigmoid(zu @ zv^T)  (bf16x3, fused sigmoid)
    {
        dim3 grid(N_UV / 128, N_UV / 128);
        mma_gemm_kernel<<<grid, 256, SMEM4>>>(zuh, zul, zvh, zvl, out,
                                              N_UV, N_UV, NCLASS);
    }
}